// round 15
// baseline (speedup 1.0000x reference)
#include <cuda_runtime.h>
#include <cuda_fp16.h>
#include <math.h>
#include <stdint.h>

#define Bc 8
#define Tc 2048
#define DMc 1024
#define Hc 8
#define SDc 64
#define INNERc 512
#define HIDc 4096
#define Mrows (Bc * Tc)
#define NCHUNK 8
#define CLEN 256

typedef __half fp16;

__device__ __align__(256) fp16  g_nh [(size_t)Mrows * DMc];
__device__ __align__(256) float g_proj[(size_t)Mrows * 2048];
__device__ __align__(256) float g_sd [(size_t)Mrows * Hc];
__device__ __align__(256) float g_pd [(size_t)Mrows * Hc];
__device__ __align__(256) fp16  g_ys [(size_t)Mrows * INNERc];
__device__ __align__(256) float g_h  [(size_t)Mrows * DMc];
__device__ __align__(256) fp16  g_fin[(size_t)Mrows * DMc];
__device__ __align__(256) fp16  g_mid[(size_t)Mrows * HIDc];
__device__ __align__(256) fp16 g_wp[2048*DMc];
__device__ __align__(256) fp16 g_wo[DMc*INNERc];
__device__ __align__(256) fp16 g_w1[HIDc*DMc];
__device__ __align__(256) fp16 g_w2[DMc*HIDc];
// chunked-scan intermediates
__device__ __align__(256) float g_lhat[(size_t)64*Tc*64];
__device__ __align__(256) float g_rt  [(size_t)64*Tc*64];
__device__ __align__(256) float g_Qt  [(size_t)64*Tc];
__device__ __align__(256) float g_PL[64*NCHUNK], g_QL[64*NCHUNK];
__device__ __align__(256) float g_uL[64*NCHUNK*64], g_rL[64*NCHUNK*64];
__device__ __align__(256) float g_Mhat[(size_t)64*NCHUNK*4096];
__device__ __align__(256) float g_s0[64*NCHUNK*64];
__device__ __align__(256) float g_M0[(size_t)64*NCHUNK*4096];

// ---------------- helpers ----------------
__device__ __forceinline__ uint32_t smem_u32(const void* p) {
    return (uint32_t)__cvta_generic_to_shared(p);
}
__device__ __forceinline__ void cp16(uint32_t dst, const void* src) {
    asm volatile("cp.async.cg.shared.global [%0], [%1], 16;\n" :: "r"(dst), "l"(src));
}
__device__ __forceinline__ void cp_commit() { asm volatile("cp.async.commit_group;\n"); }
template <int NN> __device__ __forceinline__ void cp_wait() {
    asm volatile("cp.async.wait_group %0;\n" :: "n"(NN));
}
__device__ __forceinline__ void ldm_x4(uint32_t* r, uint32_t addr) {
    asm volatile("ldmatrix.sync.aligned.m8n8.x4.shared.b16 {%0,%1,%2,%3}, [%4];"
        : "=r"(r[0]), "=r"(r[1]), "=r"(r[2]), "=r"(r[3]) : "r"(addr));
}
__device__ __forceinline__ void mma_fp16(float* d, const uint32_t* a, const uint32_t* b) {
    asm volatile("mma.sync.aligned.m16n8k16.row.col.f32.f16.f16.f32 "
        "{%0,%1,%2,%3},{%4,%5,%6,%7},{%8,%9},{%0,%1,%2,%3};"
        : "+f"(d[0]), "+f"(d[1]), "+f"(d[2]), "+f"(d[3])
        : "r"(a[0]), "r"(a[1]), "r"(a[2]), "r"(a[3]), "r"(b[0]), "r"(b[1]));
}

// ---------------- LN + fp16 out (+ optional fused sd/pd gates) --------------
template <bool GATES>
__global__ void ln_h_kernel(const float* __restrict__ X,
                            const float* __restrict__ gam,
                            const float* __restrict__ bet,
                            fp16* __restrict__ Oh,
                            const float* __restrict__ Wsd, const float* __restrict__ bsd,
                            const float* __restrict__ Wpd, const float* __restrict__ bpd,
                            float* __restrict__ SDo, float* __restrict__ PDo)
{
    int row = blockIdx.x, tid = threadIdx.x;
    const float4* xr = reinterpret_cast<const float4*>(X + (size_t)row * DMc);
    float4 v = xr[tid];
    float s = v.x + v.y + v.z + v.w;
    float q = v.x*v.x + v.y*v.y + v.z*v.z + v.w*v.w;
    int lane = tid & 31, wid = tid >> 5;
#pragma unroll
    for (int o = 16; o; o >>= 1) {
        s += __shfl_xor_sync(0xffffffffu, s, o);
        q += __shfl_xor_sync(0xffffffffu, q, o);
    }
    __shared__ float rs[8], rq[8];
    __shared__ float s_n[1024];
    __shared__ float s_part[16][17];
    if (!lane) { rs[wid] = s; rq[wid] = q; }
    __syncthreads();
    if (tid == 0) {
        float S = 0.f, Q = 0.f;
#pragma unroll
        for (int i = 0; i < 8; i++) { S += rs[i]; Q += rq[i]; }
        rs[0] = S; rq[0] = Q;
    }
    __syncthreads();
    float mu = rs[0] * (1.0f / DMc);
    float var = rq[0] * (1.0f / DMc) - mu * mu;
    float rstd = rsqrtf(var + 1e-5f);
    const float4 gg = reinterpret_cast<const float4*>(gam)[tid];
    const float4 bb = reinterpret_cast<const float4*>(bet)[tid];
    float o[4];
    o[0] = (v.x-mu)*rstd*gg.x + bb.x; o[1] = (v.y-mu)*rstd*gg.y + bb.y;
    o[2] = (v.z-mu)*rstd*gg.z + bb.z; o[3] = (v.w-mu)*rstd*gg.w + bb.w;
    size_t off = (size_t)row * DMc + tid * 4;
    __half2 h0 = __halves2half2(__float2half(o[0]), __float2half(o[1]));
    __half2 h1 = __halves2half2(__float2half(o[2]), __float2half(o[3]));
    *reinterpret_cast<uint2*>(Oh + off) = make_uint2(*(uint32_t*)&h0, *(uint32_t*)&h1);
    if (GATES) {
        *reinterpret_cast<float4*>(&s_n[tid * 4]) = make_float4(o[0], o[1], o[2], o[3]);
        __syncthreads();
        int gslot = tid & 15;
        int j = gslot & 7;
        int kc = tid >> 4;
        const float* Wg = (gslot < 8) ? Wsd : Wpd;
        float part = 0.f;
#pragma unroll 8
        for (int kk = 0; kk < 64; kk++) {
            int kx = kc * 64 + kk;
            part += s_n[kx] * Wg[(size_t)kx * Hc + j];
        }
        s_part[kc][gslot] = part;
        __syncthreads();
        if (tid < 16) {
            float sum = 0.f;
#pragma unroll
            for (int c = 0; c < 16; c++) sum += s_part[c][tid];
            int jj = tid & 7;
            float bv = (tid < 8) ? bsd[jj] : bpd[jj];
            float sig = 1.0f / (1.0f + expf(-(sum + bv)));
            float* outp = (tid < 8) ? SDo : PDo;
            outp[(size_t)row * Hc + jj] = sig;
        }
    }
}

// ---------------- weight transpose ----------------
__global__ void tsplit_kernel(const float* __restrict__ W,
                              fp16* __restrict__ Oh, int K, int N)
{
    __shared__ float t[32][33];
    int n0 = blockIdx.x * 32, k0 = blockIdx.y * 32;
    int tx = threadIdx.x, ty = threadIdx.y;
#pragma unroll
    for (int j = 0; j < 32; j += 8)
        t[ty + j][tx] = W[(size_t)(k0 + ty + j) * N + n0 + tx];
    __syncthreads();
#pragma unroll
    for (int j = 0; j < 32; j += 8)
        Oh[(size_t)(n0 + ty + j) * K + k0 + tx] = __float2half(t[tx][ty + j]);
}

__global__ void tsplit4_kernel(const float* __restrict__ Wa, const float* __restrict__ Wb,
                               const float* __restrict__ Wql, const float* __restrict__ Wqr,
                               fp16* __restrict__ Oh)
{
    int z = blockIdx.z;
    const float* W = (z == 0) ? Wa : (z == 1) ? Wb : (z == 2) ? Wql : Wqr;
    __shared__ float t[32][33];
    int n0 = blockIdx.x * 32, k0 = blockIdx.y * 32;
    int tx = threadIdx.x, ty = threadIdx.y;
#pragma unroll
    for (int j = 0; j < 32; j += 8)
        t[ty + j][tx] = W[(size_t)(k0 + ty + j) * INNERc + n0 + tx];
    __syncthreads();
#pragma unroll
    for (int j = 0; j < 32; j += 8)
        Oh[(size_t)(z * INNERc + n0 + ty + j) * DMc + k0 + tx] = __float2half(t[tx][ty + j]);
}

// ---------------- mma.sync fp16 GEMM (unchanged, measured ceiling) -----------
enum { EPI_TANH = 1, EPI_RES = 2, EPI_GELU = 3, EPI_RES_BIAS = 4 };
#define LDB 144u
#define MATB 18432u
#define STAGEB 36864u
#define NSTAGE 3
#define SMEM_DYN (3 * 36864)

template <int EPI>
__global__ __launch_bounds__(256)
void mma_gemm(const fp16* __restrict__ A, const fp16* __restrict__ B,
              float* __restrict__ C, fp16* __restrict__ Oh,
              const float* __restrict__ res, const float* __restrict__ bias,
              int M, int N, int K)
{
    extern __shared__ char smraw[];
    uint32_t sbase = smem_u32(smraw);
    int tid = threadIdx.x, lane = tid & 31, wid = tid >> 5;
    int warp_m = wid & 3, warp_n = wid >> 2;
    int bm = blockIdx.y * 128, bn = blockIdx.x * 128;

    float acc[2][8][4];
#pragma unroll
    for (int a = 0; a < 2; a++)
#pragma unroll
        for (int b = 0; b < 8; b++)
#pragma unroll
            for (int c = 0; c < 4; c++) acc[a][b][c] = 0.f;

    auto load_stage = [&](int c) {
        int k0 = c * 64;
        uint32_t st = sbase + (uint32_t)(c % NSTAGE) * STAGEB;
#pragma unroll
        for (int i = 0; i < 8; i++) {
            int id = tid + i * 256;
            int mat = id >> 10, rem = id & 1023;
            int r = rem >> 3, g = rem & 7;
            const fp16* src = mat ? B : A;
            int row = (mat ? bn : bm) + r;
            cp16(st + (uint32_t)mat * MATB + (uint32_t)r * LDB + (uint32_t)g * 16u,
                 src + (size_t)row * K + k0 + g * 8);
        }
        cp_commit();
    };

    int NC = K / 64;
    load_stage(0);
    load_stage(1);

    uint32_t a_off = (uint32_t)(warp_m * 32 + (lane & 15)) * LDB + (uint32_t)((lane >> 4) << 4);
    int bg = lane >> 3, bt = lane & 7;
    uint32_t b_off = (uint32_t)(warp_n * 64 + ((bg >> 1) << 3) + bt) * LDB + (uint32_t)((bg & 1) << 4);

    for (int c = 0; c < NC; c++) {
        cp_wait<1>();
        __syncthreads();
        if (c + 2 < NC) load_stage(c + 2);
        uint32_t st = sbase + (uint32_t)(c % NSTAGE) * STAGEB;
#pragma unroll
        for (int ks = 0; ks < 4; ks++) {
            uint32_t koff = (uint32_t)(ks << 5);
            uint32_t ar[2][4];
#pragma unroll
            for (int mt = 0; mt < 2; mt++)
                ldm_x4(ar[mt], st + a_off + (uint32_t)(mt * 16) * LDB + koff);
            uint32_t br[8][2];
#pragma unroll
            for (int jj = 0; jj < 4; jj++) {
                uint32_t r4[4];
                ldm_x4(r4, st + MATB + b_off + (uint32_t)(jj * 16) * LDB + koff);
                br[jj*2][0] = r4[0]; br[jj*2][1] = r4[1];
                br[jj*2+1][0] = r4[2]; br[jj*2+1][1] = r4[3];
            }
#pragma unroll
            for (int mt = 0; mt < 2; mt++)
#pragma unroll
                for (int nt = 0; nt < 8; nt++)
                    mma_fp16(acc[mt][nt], ar[mt], br[nt]);
        }
    }

#pragma unroll
    for (int mt = 0; mt < 2; mt++)
#pragma unroll
        for (int nt = 0; nt < 8; nt++) {
            int col = bn + warp_n * 64 + nt * 8 + (lane & 3) * 2;
            int r0 = bm + warp_m * 32 + mt * 16 + (lane >> 2);
#pragma unroll
            for (int hr = 0; hr < 2; hr++) {
                int m = r0 + hr * 8;
                float v0 = acc[mt][nt][hr*2+0], v1 = acc[mt][nt][hr*2+1];
                size_t off = (size_t)m * N + col;
                if (EPI == EPI_GELU) {
                    float2 bb = *reinterpret_cast<const float2*>(&bias[col]);
                    v0 += bb.x; v1 += bb.y;
                    const float is2 = 0.70710678118654752f;
                    v0 = 0.5f * v0 * (1.f + erff(v0 * is2));
                    v1 = 0.5f * v1 * (1.f + erff(v1 * is2));
                    __half2 hh = __halves2half2(__float2half(v0), __float2half(v1));
                    *reinterpret_cast<uint32_t*>(&Oh[off]) = *(uint32_t*)&hh;
                } else {
                    if (EPI == EPI_TANH) { v0 = tanhf(v0); v1 = tanhf(v1); }
                    else if (EPI == EPI_RES) {
                        float2 rr = *reinterpret_cast<const float2*>(&res[off]);
                        v0 += rr.x; v1 += rr.y;
                    } else if (EPI == EPI_RES_BIAS) {
                        float2 rr = *reinterpret_cast<const float2*>(&res[off]);
                        float2 bb = *reinterpret_cast<const float2*>(&bias[col]);
                        v0 += rr.x + bb.x; v1 += rr.y + bb.y;
                    }
                    *reinterpret_cast<float2*>(&C[off]) = make_float2(v0, v1);
                }
            }
        }
}

// ---------------- scan phase 1: per-chunk partial scan (zero init) -----------
// grid (128, 8): x = es(2) x h(8) x b(8), y = chunk. 256 threads = 8 warps.
// lane: eidx = lane&3, dg = lane>>2; e_loc = es*32 + w*4 + eidx; d0 = dg*8.
__global__ __launch_bounds__(256)
void scan_p1(const float* __restrict__ P,
             const float* __restrict__ SDg, const float* __restrict__ PDg,
             float* __restrict__ LHAT, float* __restrict__ RT, float* __restrict__ QT,
             float* __restrict__ PLa, float* __restrict__ QLa,
             float* __restrict__ ULa, float* __restrict__ RLa,
             float* __restrict__ MHAT)
{
    int blk = blockIdx.x, cch = blockIdx.y;
    int es = blk & 1, h = (blk >> 1) & 7, b = blk >> 4;
    int stream = b * 8 + h;
    int tid = threadIdx.x, w = tid >> 5, lane = tid & 31;
    int eidx = lane & 3, dg = lane >> 2;
    int e_loc = es * 32 + w * 4 + eidx;
    int d0 = dg * 8;
    int tC = cch * CLEN;

    __shared__ float s_a [2][8][68];
    __shared__ float s_ql[2][8][68];
    __shared__ float s_b [2][8][32];
    __shared__ float s_sp[2][8][2];

    size_t Pbase = ((size_t)b * Tc) * 2048 + (size_t)h * SDc;
    size_t spb   = ((size_t)b * Tc) * Hc + h;

    auto load_batch = [&](int t0, float* r) {
#pragma unroll
        for (int i = 0; i < 6; i++) {
            int f = tid + i * 256;
            float v = 0.f;
            if (f < 512) {
                int j = f >> 6, d = f & 63;
                v = P[Pbase + (size_t)(t0 + j) * 2048 + d];
            } else if (f < 1024) {
                int g = f - 512; int j = g >> 6, d = g & 63;
                v = P[Pbase + (size_t)(t0 + j) * 2048 + 1024 + d];
            } else if (f < 1280) {
                int g = f - 1024; int j = g >> 5, e = g & 31;
                v = P[Pbase + (size_t)(t0 + j) * 2048 + 512 + es * 32 + e];
            } else if (f < 1296) {
                int g = f - 1280; int j = g >> 1;
                v = (g & 1) ? PDg[spb + (size_t)(t0 + j) * Hc]
                            : SDg[spb + (size_t)(t0 + j) * Hc];
            }
            r[i] = v;
        }
    };
    auto store_batch = [&](int buf, const float* r) {
#pragma unroll
        for (int i = 0; i < 6; i++) {
            int f = tid + i * 256;
            if (f < 512) {
                int j = f >> 6, d = f & 63;
                s_a[buf][j][d + ((d >> 5) << 2)] = r[i];
            } else if (f < 1024) {
                int g = f - 512; int j = g >> 6, d = g & 63;
                s_ql[buf][j][d + ((d >> 5) << 2)] = r[i];
            } else if (f < 1280) {
                int g = f - 1024;
                s_b[buf][g >> 5][g & 31] = r[i];
            } else if (f < 1296) {
                int g = f - 1280;
                s_sp[buf][g >> 1][g & 1] = r[i];
            }
        }
    };

    float pair[8], state[8];
#pragma unroll
    for (int i = 0; i < 8; i++) { pair[i] = 0.f; state[i] = 0.f; }
    float rgate = 0.f, Pp = 1.f, Qq = 1.f;

    float rr[2][6];
    {
        float ra[6];
        load_batch(tC, ra);
        store_batch(0, ra);
    }
    load_batch(tC + 8, rr[0]);
    __syncthreads();

    int sbidx = d0 + ((dg >> 2) << 2);
    int ecol = w * 4 + eidx;

    for (int k = 0; k < CLEN / 8; k++) {
        int buf = k & 1;
        int t0 = tC + k * 8;
        if (k < CLEN / 8 - 2) load_batch(t0 + 16, rr[buf ^ 1]);
        if (k < CLEN / 8 - 1) store_batch(buf ^ 1, rr[buf]);
        float accv[8], rv[8], Qv[8];
#pragma unroll
        for (int j = 0; j < 8; j++) {
            float sd = s_sp[buf][j][0], pd = s_sp[buf][j][1];
            float bv = s_b[buf][j][ecol];
            // gate-product recurrences (use P_{t-1} before update)
            rgate = pd * rgate + (1.f - pd) * Pp * bv;
            rv[j] = rgate;
            Pp *= sd; Qq *= pd; Qv[j] = Qq;
            float4 q0 = *reinterpret_cast<const float4*>(&s_ql[buf][j][sbidx]);
            float4 q1 = *reinterpret_cast<const float4*>(&s_ql[buf][j][sbidx + 4]);
            float4 a0 = *reinterpret_cast<const float4*>(&s_a[buf][j][sbidx]);
            float4 a1 = *reinterpret_cast<const float4*>(&s_a[buf][j][sbidx + 4]);
            float qlv[8] = {q0.x,q0.y,q0.z,q0.w,q1.x,q1.y,q1.z,q1.w};
            float av[8]  = {a0.x,a0.y,a0.z,a0.w,a1.x,a1.y,a1.z,a1.w};
            float ompd_b = (1.f - pd) * bv;
            float acc = 0.f;
#pragma unroll
            for (int i = 0; i < 8; i++) {
                pair[i] = pd * pair[i] + ompd_b * state[i];
                acc += pair[i] * qlv[i];
            }
            float oms = 1.f - sd;
#pragma unroll
            for (int i = 0; i < 8; i++)
                state[i] = sd * state[i] + oms * av[i];
            accv[j] = acc;
        }
#pragma unroll
        for (int j = 0; j < 8; j++) accv[j] += __shfl_xor_sync(0xffffffffu, accv[j], 4);
#pragma unroll
        for (int j = 0; j < 8; j++) accv[j] += __shfl_xor_sync(0xffffffffu, accv[j], 8);
#pragma unroll
        for (int j = 0; j < 8; j++) accv[j] += __shfl_xor_sync(0xffffffffu, accv[j], 16);
        if (dg == 0) {
#pragma unroll
            for (int j = 0; j < 8; j++) {
                size_t pidx = ((size_t)stream * Tc + (t0 + j)) * 64 + e_loc;
                LHAT[pidx] = accv[j];
                RT[pidx]   = rv[j];
            }
        }
        if (es == 0 && tid == 0) {
#pragma unroll
            for (int j = 0; j < 8; j++)
                QT[(size_t)stream * Tc + t0 + j] = Qv[j];
        }
        __syncthreads();
    }

    // chunk-final boundary values
    size_t bidx = (size_t)(stream * NCHUNK + cch);
    if (es == 0 && tid == 0) { PLa[bidx] = Pp; QLa[bidx] = Qq; }
    if (es == 0 && w == 0 && eidx == 0) {
#pragma unroll
        for (int i = 0; i < 8; i++) ULa[bidx * 64 + d0 + i] = state[i];
    }
    if (dg == 0) RLa[bidx * 64 + e_loc] = rgate;
#pragma unroll
    for (int i = 0; i < 8; i++)
        MHAT[(bidx << 12) + (size_t)(d0 + i) * 64 + e_loc] = pair[i];
}

// ---------------- scan phase 2: boundary propagation (tiny) ------------------
__global__ __launch_bounds__(256)
void scan_p2(const float* __restrict__ PLa, const float* __restrict__ QLa,
             const float* __restrict__ ULa, const float* __restrict__ RLa,
             const float* __restrict__ MHAT,
             float* __restrict__ S0a, float* __restrict__ M0a)
{
    int stream = blockIdx.x, tid = threadIdx.x;
    __shared__ float s0[64];
    float m[16];
#pragma unroll
    for (int i = 0; i < 16; i++) m[i] = 0.f;
    if (tid < 64) s0[tid] = 0.f;
    __syncthreads();
    int d_ = tid >> 2, e0 = (tid & 3) * 16;
    for (int c = 0; c < NCHUNK; c++) {
        size_t bidx = (size_t)(stream * NCHUNK + c);
        if (tid < 64) S0a[bidx * 64 + tid] = s0[tid];
#pragma unroll
        for (int i = 0; i < 16; i++)
            M0a[(bidx << 12) + (size_t)d_ * 64 + e0 + i] = m[i];
        float QL = QLa[bidx], PL = PLa[bidx];
        float s0d = s0[d_];
#pragma unroll
        for (int i = 0; i < 16; i++)
            m[i] = QL * m[i] + s0d * RLa[bidx * 64 + e0 + i]
                 + MHAT[(bidx << 12) + (size_t)d_ * 64 + e0 + i];
        __syncthreads();
        if (tid < 64) s0[tid] = PL * s0[tid] + ULa[bidx * 64 + tid];
        __syncthreads();
    }
}

// ---------------- scan phase 3: parallel correction + output -----------------
// grid (32, 64): x = t-tile of 64 steps, y = stream. 256 thr: tg=tid>>6, e=tid&63.
__global__ __launch_bounds__(256)
void scan_p3(const float* __restrict__ Pr,
             const float* __restrict__ LHAT, const float* __restrict__ RT,
             const float* __restrict__ QT,
             const float* __restrict__ S0a, const float* __restrict__ M0a,
             fp16* __restrict__ Y)
{
    int tt0 = blockIdx.x * 64;
    int stream = blockIdx.y;
    int cch = tt0 / CLEN;
    int b = stream >> 3, h = stream & 7;
    int tid = threadIdx.x, tg = tid >> 6, e = tid & 63;
    __shared__ float sM0[64][64];    // [d][e]
    __shared__ float sql[64][64];    // [tloc][d]
    __shared__ float ss0[64];
    size_t bidx = (size_t)(stream * NCHUNK + cch);
#pragma unroll
    for (int i = 0; i < 16; i++) {
        int f = tid + i * 256;
        sM0[f >> 6][f & 63] = M0a[(bidx << 12) + f];
    }
    if (tid < 64) ss0[tid] = S0a[bidx * 64 + tid];
    size_t Pbase = ((size_t)b * Tc) * 2048 + (size_t)h * SDc;
#pragma unroll
    for (int i = 0; i < 16; i++) {
        int f = tid + i * 256;
        int tloc = f >> 6, d = f & 63;
        sql[tloc][d] = Pr[Pbase + (size_t)(tt0 + tloc) * 2048 + 1024 + d];
    }
    __syncthreads();
    size_t outb = ((size_t)b * Tc) * INNERc + (size_t)h * SDc + e;
    for (int kk = 0; kk < 16; kk++) {
        int tloc = tg * 16 + kk;
        int t = tt0 + tloc;
        float mv0 = 0.f, mv1 = 0.f, dot0 = 0.f, dot1 = 0.f;
#pragma unroll
        for (int d = 0; d < 64; d += 2) {
            float q0 = sql[tloc][d], q1 = sql[tloc][d + 1];
            mv0 += sM0[d][e] * q0;   mv1 += sM0[d + 1][e] * q1;
            dot0 += ss0[d] * q0;     dot1 += ss0[d + 1] * q1;
        }
        float mv = mv0 + mv1, dot = dot0 + dot1;
        size_t pidx = (size_t)stream * Tc + t;
        float lh = LHAT[pidx * 64 + e];
        float rv = RT[pidx * 64 + e];
        float Qv = QT[pidx];
        float qr = Pr[Pbase + (size_t)t * 2048 + 1536 + e];
        float outv = qr * (Qv * mv + dot * rv + lh);
        Y[outb + (size_t)t * INNERc] = __float2half(outv);
    }
}

// ---------------- launch ----------------
static float* symf(const void* s) { void* p = 0; cudaGetSymbolAddress(&p, s); return (float*)p; }
static fp16*  symh(const void* s) { void* p = 0; cudaGetSymbolAddress(&p, s); return (fp16*)p; }

extern "C" void kernel_launch(void* const* d_in, const int* in_sizes, int n_in,
                              void* d_out, int out_size)
{
    const float* x    = (const float*)d_in[0];
    const float* ln_g = (const float*)d_in[1];
    const float* ln_b = (const float*)d_in[2];
    const float* ffn_g= (const float*)d_in[3];
    const float* ffn_b= (const float*)d_in[4];
    const float* Wa   = (const float*)d_in[5];
    const float* Wb   = (const float*)d_in[6];
    const float* Wql  = (const float*)d_in[7];
    const float* Wqr  = (const float*)d_in[8];
    const float* Wsd  = (const float*)d_in[9];
    const float* bsd  = (const float*)d_in[10];
    const float* Wpd  = (const float*)d_in[11];
    const float* bpd  = (const float*)d_in[12];
    const float* Wout = (const float*)d_in[13];
    const float* W1   = (const float*)d_in[14];
    const float* b1   = (const float*)d_in[15];
    const float* W2   = (const float*)d_in[16];
    const float* b2   = (const float*)d_in[17];
    float* out = (float*)d_out;

    cudaFuncSetAttribute(mma_gemm<EPI_TANH>, cudaFuncAttributeMaxDynamicSharedMemorySize, SMEM_DYN);
    cudaFuncSetAttribute(mma_gemm<EPI_RES>, cudaFuncAttributeMaxDynamicSharedMemorySize, SMEM_DYN);
    cudaFuncSetAttribute(mma_gemm<EPI_GELU>, cudaFuncAttributeMaxDynamicSharedMemorySize, SMEM_DYN);
    cudaFuncSetAttribute(mma_gemm<EPI_RES_BIAS>, cudaFuncAttributeMaxDynamicSharedMemorySize, SMEM_DYN);

    dim3 tb(32, 8);
    // 1: LN + fused gates; 2: proj weights; 3: proj GEMM
    ln_h_kernel<true><<<Mrows, 256>>>(x, ln_g, ln_b, symh(g_nh),
                                      Wsd, bsd, Wpd, bpd, symf(g_sd), symf(g_pd));
    tsplit4_kernel<<<dim3(INNERc/32, DMc/32, 4), tb>>>(Wa, Wb, Wql, Wqr, symh(g_wp));
    {
        dim3 grid(2048/128, Mrows/128);
        mma_gemm<EPI_TANH><<<grid, 256, SMEM_DYN>>>(symh(g_nh), symh(g_wp),
            symf(g_proj), nullptr, nullptr, nullptr, Mrows, 2048, DMc);
    }
    // 4: scan phase 1 <- profiled
    scan_p1<<<dim3(128, NCHUNK), 256>>>(symf(g_proj), symf(g_sd), symf(g_pd),
        symf(g_lhat), symf(g_rt), symf(g_Qt),
        symf(g_PL), symf(g_QL), symf(g_uL), symf(g_rL), symf(g_Mhat));
    // 5: boundary propagation; 6: correction + output
    scan_p2<<<64, 256>>>(symf(g_PL), symf(g_QL), symf(g_uL), symf(g_rL),
                         symf(g_Mhat), symf(g_s0), symf(g_M0));
    scan_p3<<<dim3(Tc/64, 64), 256>>>(symf(g_proj), symf(g_lhat), symf(g_rt),
                                      symf(g_Qt), symf(g_s0), symf(g_M0), symh(g_ys));

    tsplit_kernel<<<dim3(DMc/32, INNERc/32), tb>>>(Wout, symh(g_wo), INNERc, DMc);
    {
        dim3 grid(DMc/128, Mrows/128);
        mma_gemm<EPI_RES><<<grid, 256, SMEM_DYN>>>(symh(g_ys), symh(g_wo),
            symf(g_h), nullptr, x, nullptr, Mrows, DMc, INNERc);
    }
    ln_h_kernel<false><<<Mrows, 256>>>(symf(g_h), ffn_g, ffn_b, symh(g_fin),
                                       nullptr, nullptr, nullptr, nullptr, nullptr, nullptr);
    tsplit_kernel<<<dim3(HIDc/32, DMc/32), tb>>>(W1, symh(g_w1), DMc, HIDc);
    {
        dim3 grid(HIDc/128, Mrows/128);
        mma_gemm<EPI_GELU><<<grid, 256, SMEM_DYN>>>(symh(g_fin), symh(g_w1),
            nullptr, symh(g_mid), nullptr, b1, Mrows, HIDc, DMc);
    }
    tsplit_kernel<<<dim3(DMc/32, HIDc/32), tb>>>(W2, symh(g_w2), HIDc, DMc);
    {
        dim3 grid(DMc/128, Mrows/128);
        mma_gemm<EPI_RES_BIAS><<<grid, 256, SMEM_DYN>>>(symh(g_mid), symh(g_w2),
            out, nullptr, symf(g_h), b2, Mrows, DMc, HIDc);
    }
}

// round 16
// speedup vs baseline: 1.0421x; 1.0421x over previous
#include <cuda_runtime.h>
#include <cuda_fp16.h>
#include <math.h>
#include <stdint.h>

#define Bc 8
#define Tc 2048
#define DMc 1024
#define Hc 8
#define SDc 64
#define INNERc 512
#define HIDc 4096
#define Mrows (Bc * Tc)
#define NCHUNK 16
#define CLEN 128

typedef __half fp16;

__device__ __align__(256) fp16  g_nh [(size_t)Mrows * DMc];
__device__ __align__(256) float g_proj[(size_t)Mrows * 2048];
__device__ __align__(256) float g_sd [(size_t)Mrows * Hc];
__device__ __align__(256) float g_pd [(size_t)Mrows * Hc];
__device__ __align__(256) fp16  g_ys [(size_t)Mrows * INNERc];
__device__ __align__(256) float g_h  [(size_t)Mrows * DMc];
__device__ __align__(256) fp16  g_fin[(size_t)Mrows * DMc];
__device__ __align__(256) fp16  g_mid[(size_t)Mrows * HIDc];
__device__ __align__(256) fp16 g_wp[2048*DMc];
__device__ __align__(256) fp16 g_wo[DMc*INNERc];
__device__ __align__(256) fp16 g_w1[HIDc*DMc];
__device__ __align__(256) fp16 g_w2[DMc*HIDc];
// chunked-scan intermediates
__device__ __align__(256) float g_lhat[(size_t)64*Tc*64];
__device__ __align__(256) float g_rt  [(size_t)64*Tc*64];
__device__ __align__(256) float g_Qt  [(size_t)64*Tc];
__device__ __align__(256) float g_PL[64*NCHUNK], g_QL[64*NCHUNK];
__device__ __align__(256) float g_uL[64*NCHUNK*64], g_rL[64*NCHUNK*64];
__device__ __align__(256) float g_Mhat[(size_t)64*NCHUNK*4096];
__device__ __align__(256) float g_s0[64*NCHUNK*64];
__device__ __align__(256) float g_M0[(size_t)64*NCHUNK*4096];

// ---------------- helpers ----------------
__device__ __forceinline__ uint32_t smem_u32(const void* p) {
    return (uint32_t)__cvta_generic_to_shared(p);
}
__device__ __forceinline__ void cp16(uint32_t dst, const void* src) {
    asm volatile("cp.async.cg.shared.global [%0], [%1], 16;\n" :: "r"(dst), "l"(src));
}
__device__ __forceinline__ void cp_commit() { asm volatile("cp.async.commit_group;\n"); }
template <int NN> __device__ __forceinline__ void cp_wait() {
    asm volatile("cp.async.wait_group %0;\n" :: "n"(NN));
}
__device__ __forceinline__ void ldm_x4(uint32_t* r, uint32_t addr) {
    asm volatile("ldmatrix.sync.aligned.m8n8.x4.shared.b16 {%0,%1,%2,%3}, [%4];"
        : "=r"(r[0]), "=r"(r[1]), "=r"(r[2]), "=r"(r[3]) : "r"(addr));
}
__device__ __forceinline__ void mma_fp16(float* d, const uint32_t* a, const uint32_t* b) {
    asm volatile("mma.sync.aligned.m16n8k16.row.col.f32.f16.f16.f32 "
        "{%0,%1,%2,%3},{%4,%5,%6,%7},{%8,%9},{%0,%1,%2,%3};"
        : "+f"(d[0]), "+f"(d[1]), "+f"(d[2]), "+f"(d[3])
        : "r"(a[0]), "r"(a[1]), "r"(a[2]), "r"(a[3]), "r"(b[0]), "r"(b[1]));
}

// ---------------- LN + fp16 out (+ optional fused sd/pd gates) --------------
template <bool GATES>
__global__ void ln_h_kernel(const float* __restrict__ X,
                            const float* __restrict__ gam,
                            const float* __restrict__ bet,
                            fp16* __restrict__ Oh,
                            const float* __restrict__ Wsd, const float* __restrict__ bsd,
                            const float* __restrict__ Wpd, const float* __restrict__ bpd,
                            float* __restrict__ SDo, float* __restrict__ PDo)
{
    int row = blockIdx.x, tid = threadIdx.x;
    const float4* xr = reinterpret_cast<const float4*>(X + (size_t)row * DMc);
    float4 v = xr[tid];
    float s = v.x + v.y + v.z + v.w;
    float q = v.x*v.x + v.y*v.y + v.z*v.z + v.w*v.w;
    int lane = tid & 31, wid = tid >> 5;
#pragma unroll
    for (int o = 16; o; o >>= 1) {
        s += __shfl_xor_sync(0xffffffffu, s, o);
        q += __shfl_xor_sync(0xffffffffu, q, o);
    }
    __shared__ float rs[8], rq[8];
    __shared__ float s_n[1024];
    __shared__ float s_part[16][17];
    if (!lane) { rs[wid] = s; rq[wid] = q; }
    __syncthreads();
    if (tid == 0) {
        float S = 0.f, Q = 0.f;
#pragma unroll
        for (int i = 0; i < 8; i++) { S += rs[i]; Q += rq[i]; }
        rs[0] = S; rq[0] = Q;
    }
    __syncthreads();
    float mu = rs[0] * (1.0f / DMc);
    float var = rq[0] * (1.0f / DMc) - mu * mu;
    float rstd = rsqrtf(var + 1e-5f);
    const float4 gg = reinterpret_cast<const float4*>(gam)[tid];
    const float4 bb = reinterpret_cast<const float4*>(bet)[tid];
    float o[4];
    o[0] = (v.x-mu)*rstd*gg.x + bb.x; o[1] = (v.y-mu)*rstd*gg.y + bb.y;
    o[2] = (v.z-mu)*rstd*gg.z + bb.z; o[3] = (v.w-mu)*rstd*gg.w + bb.w;
    size_t off = (size_t)row * DMc + tid * 4;
    __half2 h0 = __halves2half2(__float2half(o[0]), __float2half(o[1]));
    __half2 h1 = __halves2half2(__float2half(o[2]), __float2half(o[3]));
    *reinterpret_cast<uint2*>(Oh + off) = make_uint2(*(uint32_t*)&h0, *(uint32_t*)&h1);
    if (GATES) {
        *reinterpret_cast<float4*>(&s_n[tid * 4]) = make_float4(o[0], o[1], o[2], o[3]);
        __syncthreads();
        int gslot = tid & 15;
        int j = gslot & 7;
        int kc = tid >> 4;
        const float* Wg = (gslot < 8) ? Wsd : Wpd;
        float part = 0.f;
#pragma unroll 8
        for (int kk = 0; kk < 64; kk++) {
            int kx = kc * 64 + kk;
            part += s_n[kx] * Wg[(size_t)kx * Hc + j];
        }
        s_part[kc][gslot] = part;
        __syncthreads();
        if (tid < 16) {
            float sum = 0.f;
#pragma unroll
            for (int c = 0; c < 16; c++) sum += s_part[c][tid];
            int jj = tid & 7;
            float bv = (tid < 8) ? bsd[jj] : bpd[jj];
            float sig = 1.0f / (1.0f + expf(-(sum + bv)));
            float* outp = (tid < 8) ? SDo : PDo;
            outp[(size_t)row * Hc + jj] = sig;
        }
    }
}

// ---------------- weight transpose ----------------
__global__ void tsplit_kernel(const float* __restrict__ W,
                              fp16* __restrict__ Oh, int K, int N)
{
    __shared__ float t[32][33];
    int n0 = blockIdx.x * 32, k0 = blockIdx.y * 32;
    int tx = threadIdx.x, ty = threadIdx.y;
#pragma unroll
    for (int j = 0; j < 32; j += 8)
        t[ty + j][tx] = W[(size_t)(k0 + ty + j) * N + n0 + tx];
    __syncthreads();
#pragma unroll
    for (int j = 0; j < 32; j += 8)
        Oh[(size_t)(n0 + ty + j) * K + k0 + tx] = __float2half(t[tx][ty + j]);
}

__global__ void tsplit4_kernel(const float* __restrict__ Wa, const float* __restrict__ Wb,
                               const float* __restrict__ Wql, const float* __restrict__ Wqr,
                               fp16* __restrict__ Oh)
{
    int z = blockIdx.z;
    const float* W = (z == 0) ? Wa : (z == 1) ? Wb : (z == 2) ? Wql : Wqr;
    __shared__ float t[32][33];
    int n0 = blockIdx.x * 32, k0 = blockIdx.y * 32;
    int tx = threadIdx.x, ty = threadIdx.y;
#pragma unroll
    for (int j = 0; j < 32; j += 8)
        t[ty + j][tx] = W[(size_t)(k0 + ty + j) * INNERc + n0 + tx];
    __syncthreads();
#pragma unroll
    for (int j = 0; j < 32; j += 8)
        Oh[(size_t)(z * INNERc + n0 + ty + j) * DMc + k0 + tx] = __float2half(t[tx][ty + j]);
}

// ---------------- mma.sync fp16 GEMM (unchanged, measured ceiling) -----------
enum { EPI_TANH = 1, EPI_RES = 2, EPI_GELU = 3, EPI_RES_BIAS = 4 };
#define LDB 144u
#define MATB 18432u
#define STAGEB 36864u
#define NSTAGE 3
#define SMEM_DYN (3 * 36864)

template <int EPI>
__global__ __launch_bounds__(256)
void mma_gemm(const fp16* __restrict__ A, const fp16* __restrict__ B,
              float* __restrict__ C, fp16* __restrict__ Oh,
              const float* __restrict__ res, const float* __restrict__ bias,
              int M, int N, int K)
{
    extern __shared__ char smraw[];
    uint32_t sbase = smem_u32(smraw);
    int tid = threadIdx.x, lane = tid & 31, wid = tid >> 5;
    int warp_m = wid & 3, warp_n = wid >> 2;
    int bm = blockIdx.y * 128, bn = blockIdx.x * 128;

    float acc[2][8][4];
#pragma unroll
    for (int a = 0; a < 2; a++)
#pragma unroll
        for (int b = 0; b < 8; b++)
#pragma unroll
            for (int c = 0; c < 4; c++) acc[a][b][c] = 0.f;

    auto load_stage = [&](int c) {
        int k0 = c * 64;
        uint32_t st = sbase + (uint32_t)(c % NSTAGE) * STAGEB;
#pragma unroll
        for (int i = 0; i < 8; i++) {
            int id = tid + i * 256;
            int mat = id >> 10, rem = id & 1023;
            int r = rem >> 3, g = rem & 7;
            const fp16* src = mat ? B : A;
            int row = (mat ? bn : bm) + r;
            cp16(st + (uint32_t)mat * MATB + (uint32_t)r * LDB + (uint32_t)g * 16u,
                 src + (size_t)row * K + k0 + g * 8);
        }
        cp_commit();
    };

    int NC = K / 64;
    load_stage(0);
    load_stage(1);

    uint32_t a_off = (uint32_t)(warp_m * 32 + (lane & 15)) * LDB + (uint32_t)((lane >> 4) << 4);
    int bg = lane >> 3, bt = lane & 7;
    uint32_t b_off = (uint32_t)(warp_n * 64 + ((bg >> 1) << 3) + bt) * LDB + (uint32_t)((bg & 1) << 4);

    for (int c = 0; c < NC; c++) {
        cp_wait<1>();
        __syncthreads();
        if (c + 2 < NC) load_stage(c + 2);
        uint32_t st = sbase + (uint32_t)(c % NSTAGE) * STAGEB;
#pragma unroll
        for (int ks = 0; ks < 4; ks++) {
            uint32_t koff = (uint32_t)(ks << 5);
            uint32_t ar[2][4];
#pragma unroll
            for (int mt = 0; mt < 2; mt++)
                ldm_x4(ar[mt], st + a_off + (uint32_t)(mt * 16) * LDB + koff);
            uint32_t br[8][2];
#pragma unroll
            for (int jj = 0; jj < 4; jj++) {
                uint32_t r4[4];
                ldm_x4(r4, st + MATB + b_off + (uint32_t)(jj * 16) * LDB + koff);
                br[jj*2][0] = r4[0]; br[jj*2][1] = r4[1];
                br[jj*2+1][0] = r4[2]; br[jj*2+1][1] = r4[3];
            }
#pragma unroll
            for (int mt = 0; mt < 2; mt++)
#pragma unroll
                for (int nt = 0; nt < 8; nt++)
                    mma_fp16(acc[mt][nt], ar[mt], br[nt]);
        }
    }

#pragma unroll
    for (int mt = 0; mt < 2; mt++)
#pragma unroll
        for (int nt = 0; nt < 8; nt++) {
            int col = bn + warp_n * 64 + nt * 8 + (lane & 3) * 2;
            int r0 = bm + warp_m * 32 + mt * 16 + (lane >> 2);
#pragma unroll
            for (int hr = 0; hr < 2; hr++) {
                int m = r0 + hr * 8;
                float v0 = acc[mt][nt][hr*2+0], v1 = acc[mt][nt][hr*2+1];
                size_t off = (size_t)m * N + col;
                if (EPI == EPI_GELU) {
                    float2 bb = *reinterpret_cast<const float2*>(&bias[col]);
                    v0 += bb.x; v1 += bb.y;
                    const float is2 = 0.70710678118654752f;
                    v0 = 0.5f * v0 * (1.f + erff(v0 * is2));
                    v1 = 0.5f * v1 * (1.f + erff(v1 * is2));
                    __half2 hh = __halves2half2(__float2half(v0), __float2half(v1));
                    *reinterpret_cast<uint32_t*>(&Oh[off]) = *(uint32_t*)&hh;
                } else {
                    if (EPI == EPI_TANH) { v0 = tanhf(v0); v1 = tanhf(v1); }
                    else if (EPI == EPI_RES) {
                        float2 rr = *reinterpret_cast<const float2*>(&res[off]);
                        v0 += rr.x; v1 += rr.y;
                    } else if (EPI == EPI_RES_BIAS) {
                        float2 rr = *reinterpret_cast<const float2*>(&res[off]);
                        float2 bb = *reinterpret_cast<const float2*>(&bias[col]);
                        v0 += rr.x + bb.x; v1 += rr.y + bb.y;
                    }
                    *reinterpret_cast<float2*>(&C[off]) = make_float2(v0, v1);
                }
            }
        }
}

// ---------------- scan phase 1: per-chunk partial scan (zero init) -----------
// grid (128, NCHUNK): x = es(2) x h(8) x b(8), y = chunk. 256 threads = 8 warps.
__global__ __launch_bounds__(256)
void scan_p1(const float* __restrict__ P,
             const float* __restrict__ SDg, const float* __restrict__ PDg,
             float* __restrict__ LHAT, float* __restrict__ RT, float* __restrict__ QT,
             float* __restrict__ PLa, float* __restrict__ QLa,
             float* __restrict__ ULa, float* __restrict__ RLa,
             float* __restrict__ MHAT)
{
    int blk = blockIdx.x, cch = blockIdx.y;
    int es = blk & 1, h = (blk >> 1) & 7, b = blk >> 4;
    int stream = b * 8 + h;
    int tid = threadIdx.x, w = tid >> 5, lane = tid & 31;
    int eidx = lane & 3, dg = lane >> 2;
    int e_loc = es * 32 + w * 4 + eidx;
    int d0 = dg * 8;
    int tC = cch * CLEN;

    __shared__ float s_a [2][8][68];
    __shared__ float s_ql[2][8][68];
    __shared__ float s_b [2][8][32];
    __shared__ float s_sp[2][8][2];

    size_t Pbase = ((size_t)b * Tc) * 2048 + (size_t)h * SDc;
    size_t spb   = ((size_t)b * Tc) * Hc + h;

    auto load_batch = [&](int t0, float* r) {
#pragma unroll
        for (int i = 0; i < 6; i++) {
            int f = tid + i * 256;
            float v = 0.f;
            if (f < 512) {
                int j = f >> 6, d = f & 63;
                v = P[Pbase + (size_t)(t0 + j) * 2048 + d];
            } else if (f < 1024) {
                int g = f - 512; int j = g >> 6, d = g & 63;
                v = P[Pbase + (size_t)(t0 + j) * 2048 + 1024 + d];
            } else if (f < 1280) {
                int g = f - 1024; int j = g >> 5, e = g & 31;
                v = P[Pbase + (size_t)(t0 + j) * 2048 + 512 + es * 32 + e];
            } else if (f < 1296) {
                int g = f - 1280; int j = g >> 1;
                v = (g & 1) ? PDg[spb + (size_t)(t0 + j) * Hc]
                            : SDg[spb + (size_t)(t0 + j) * Hc];
            }
            r[i] = v;
        }
    };
    auto store_batch = [&](int buf, const float* r) {
#pragma unroll
        for (int i = 0; i < 6; i++) {
            int f = tid + i * 256;
            if (f < 512) {
                int j = f >> 6, d = f & 63;
                s_a[buf][j][d + ((d >> 5) << 2)] = r[i];
            } else if (f < 1024) {
                int g = f - 512; int j = g >> 6, d = g & 63;
                s_ql[buf][j][d + ((d >> 5) << 2)] = r[i];
            } else if (f < 1280) {
                int g = f - 1024;
                s_b[buf][g >> 5][g & 31] = r[i];
            } else if (f < 1296) {
                int g = f - 1280;
                s_sp[buf][g >> 1][g & 1] = r[i];
            }
        }
    };

    float pair[8], state[8];
#pragma unroll
    for (int i = 0; i < 8; i++) { pair[i] = 0.f; state[i] = 0.f; }
    float rgate = 0.f, Pp = 1.f, Qq = 1.f;

    float rr[2][6];
    {
        float ra[6];
        load_batch(tC, ra);
        store_batch(0, ra);
    }
    load_batch(tC + 8, rr[0]);
    __syncthreads();

    int sbidx = d0 + ((dg >> 2) << 2);
    int ecol = w * 4 + eidx;

    for (int k = 0; k < CLEN / 8; k++) {
        int buf = k & 1;
        int t0 = tC + k * 8;
        if (k < CLEN / 8 - 2) load_batch(t0 + 16, rr[buf ^ 1]);
        if (k < CLEN / 8 - 1) store_batch(buf ^ 1, rr[buf]);
        float accv[8], rv[8], Qv[8];
#pragma unroll
        for (int j = 0; j < 8; j++) {
            float sd = s_sp[buf][j][0], pd = s_sp[buf][j][1];
            float bv = s_b[buf][j][ecol];
            rgate = pd * rgate + (1.f - pd) * Pp * bv;
            rv[j] = rgate;
            Pp *= sd; Qq *= pd; Qv[j] = Qq;
            float4 q0 = *reinterpret_cast<const float4*>(&s_ql[buf][j][sbidx]);
            float4 q1 = *reinterpret_cast<const float4*>(&s_ql[buf][j][sbidx + 4]);
            float4 a0 = *reinterpret_cast<const float4*>(&s_a[buf][j][sbidx]);
            float4 a1 = *reinterpret_cast<const float4*>(&s_a[buf][j][sbidx + 4]);
            float qlv[8] = {q0.x,q0.y,q0.z,q0.w,q1.x,q1.y,q1.z,q1.w};
            float av[8]  = {a0.x,a0.y,a0.z,a0.w,a1.x,a1.y,a1.z,a1.w};
            float ompd_b = (1.f - pd) * bv;
            float acc = 0.f;
#pragma unroll
            for (int i = 0; i < 8; i++) {
                pair[i] = pd * pair[i] + ompd_b * state[i];
                acc += pair[i] * qlv[i];
            }
            float oms = 1.f - sd;
#pragma unroll
            for (int i = 0; i < 8; i++)
                state[i] = sd * state[i] + oms * av[i];
            accv[j] = acc;
        }
#pragma unroll
        for (int j = 0; j < 8; j++) accv[j] += __shfl_xor_sync(0xffffffffu, accv[j], 4);
#pragma unroll
        for (int j = 0; j < 8; j++) accv[j] += __shfl_xor_sync(0xffffffffu, accv[j], 8);
#pragma unroll
        for (int j = 0; j < 8; j++) accv[j] += __shfl_xor_sync(0xffffffffu, accv[j], 16);
        if (dg == 0) {
#pragma unroll
            for (int j = 0; j < 8; j++) {
                size_t pidx = ((size_t)stream * Tc + (t0 + j)) * 64 + e_loc;
                LHAT[pidx] = accv[j];
                RT[pidx]   = rv[j];
            }
        }
        if (es == 0 && tid == 0) {
#pragma unroll
            for (int j = 0; j < 8; j++)
                QT[(size_t)stream * Tc + t0 + j] = Qv[j];
        }
        __syncthreads();
    }

    size_t bidx = (size_t)(stream * NCHUNK + cch);
    if (es == 0 && tid == 0) { PLa[bidx] = Pp; QLa[bidx] = Qq; }
    if (es == 0 && w == 0 && eidx == 0) {
#pragma unroll
        for (int i = 0; i < 8; i++) ULa[bidx * 64 + d0 + i] = state[i];
    }
    if (dg == 0) RLa[bidx * 64 + e_loc] = rgate;
#pragma unroll
    for (int i = 0; i < 8; i++)
        MHAT[(bidx << 12) + (size_t)(d0 + i) * 64 + e_loc] = pair[i];
}

// ---------------- scan phase 2: boundary propagation (tiny) ------------------
__global__ __launch_bounds__(256)
void scan_p2(const float* __restrict__ PLa, const float* __restrict__ QLa,
             const float* __restrict__ ULa, const float* __restrict__ RLa,
             const float* __restrict__ MHAT,
             float* __restrict__ S0a, float* __restrict__ M0a)
{
    int stream = blockIdx.x, tid = threadIdx.x;
    __shared__ float s0[64];
    float m[16];
#pragma unroll
    for (int i = 0; i < 16; i++) m[i] = 0.f;
    if (tid < 64) s0[tid] = 0.f;
    __syncthreads();
    int d_ = tid >> 2, e0 = (tid & 3) * 16;
    for (int c = 0; c < NCHUNK; c++) {
        size_t bidx = (size_t)(stream * NCHUNK + c);
        if (tid < 64) S0a[bidx * 64 + tid] = s0[tid];
#pragma unroll
        for (int i = 0; i < 16; i++)
            M0a[(bidx << 12) + (size_t)d_ * 64 + e0 + i] = m[i];
        float QL = QLa[bidx], PL = PLa[bidx];
        float s0d = s0[d_];
#pragma unroll
        for (int i = 0; i < 16; i++)
            m[i] = QL * m[i] + s0d * RLa[bidx * 64 + e0 + i]
                 + MHAT[(bidx << 12) + (size_t)d_ * 64 + e0 + i];
        __syncthreads();
        if (tid < 64) s0[tid] = PL * s0[tid] + ULa[bidx * 64 + tid];
        __syncthreads();
    }
}

// ---------------- scan phase 3: parallel correction + output -----------------
// grid (32, 64): x = t-tile of 64 steps, y = stream. 256 thr: tg=tid>>6, e=tid&63.
__global__ __launch_bounds__(256)
void scan_p3(const float* __restrict__ Pr,
             const float* __restrict__ LHAT, const float* __restrict__ RT,
             const float* __restrict__ QT,
             const float* __restrict__ S0a, const float* __restrict__ M0a,
             fp16* __restrict__ Y)
{
    int tt0 = blockIdx.x * 64;
    int stream = blockIdx.y;
    int cch = tt0 / CLEN;
    int b = stream >> 3, h = stream & 7;
    int tid = threadIdx.x, tg = tid >> 6, e = tid & 63;
    __shared__ float sM0[64][64];    // [d][e]
    __shared__ float sql[64][64];    // [tloc][d]
    __shared__ float ss0[64];
    __shared__ float sdot[64];
    size_t bidx = (size_t)(stream * NCHUNK + cch);
#pragma unroll
    for (int i = 0; i < 16; i++) {
        int f = tid + i * 256;
        sM0[f >> 6][f & 63] = M0a[(bidx << 12) + f];
    }
    if (tid < 64) ss0[tid] = S0a[bidx * 64 + tid];
    size_t Pbase = ((size_t)b * Tc) * 2048 + (size_t)h * SDc;
#pragma unroll
    for (int i = 0; i < 16; i++) {
        int f = tid + i * 256;
        int tloc = f >> 6, d = f & 63;
        sql[tloc][d] = Pr[Pbase + (size_t)(tt0 + tloc) * 2048 + 1024 + d];
    }
    __syncthreads();
    // cooperative per-t dots: dot_t = s0 . q_t (e-independent)
    if (tid < 64) {
        float dd = 0.f;
#pragma unroll 8
        for (int d = 0; d < 64; d++) dd += ss0[d] * sql[tid][d];
        sdot[tid] = dd;
    }
    __syncthreads();
    // d-outer register-blocked matvec: mv[kk] = sum_d M0[d][e] * q_{tg*16+kk}[d]
    float mv[16];
#pragma unroll
    for (int kk = 0; kk < 16; kk++) mv[kk] = 0.f;
    int tbase = tg * 16;
#pragma unroll 4
    for (int d = 0; d < 64; d++) {
        float m0 = sM0[d][e];
#pragma unroll
        for (int kk = 0; kk < 16; kk++)
            mv[kk] += m0 * sql[tbase + kk][d];
    }
    size_t outb = ((size_t)b * Tc) * INNERc + (size_t)h * SDc + e;
#pragma unroll
    for (int kk = 0; kk < 16; kk++) {
        int tloc = tbase + kk;
        int t = tt0 + tloc;
        size_t pidx = (size_t)stream * Tc + t;
        float lh = LHAT[pidx * 64 + e];
        float rv = RT[pidx * 64 + e];
        float Qv = QT[pidx];
        float qr = Pr[Pbase + (size_t)t * 2048 + 1536 + e];
        float outv = qr * (Qv * mv[kk] + sdot[tloc] * rv + lh);
        Y[outb + (size_t)t * INNERc] = __float2half(outv);
    }
}

// ---------------- launch ----------------
static float* symf(const void* s) { void* p = 0; cudaGetSymbolAddress(&p, s); return (float*)p; }
static fp16*  symh(const void* s) { void* p = 0; cudaGetSymbolAddress(&p, s); return (fp16*)p; }

extern "C" void kernel_launch(void* const* d_in, const int* in_sizes, int n_in,
                              void* d_out, int out_size)
{
    const float* x    = (const float*)d_in[0];
    const float* ln_g = (const float*)d_in[1];
    const float* ln_b = (const float*)d_in[2];
    const float* ffn_g= (const float*)d_in[3];
    const float* ffn_b= (const float*)d_in[4];
    const float* Wa   = (const float*)d_in[5];
    const float* Wb   = (const float*)d_in[6];
    const float* Wql  = (const float*)d_in[7];
    const float* Wqr  = (const float*)d_in[8];
    const float* Wsd  = (const float*)d_in[9];
    const float* bsd  = (const float*)d_in[10];
    const float* Wpd  = (const float*)d_in[11];
    const float* bpd  = (const float*)d_in[12];
    const float* Wout = (const float*)d_in[13];
    const float* W1   = (const float*)d_in[14];
    const float* b1   = (const float*)d_in[15];
    const float* W2   = (const float*)d_in[16];
    const float* b2   = (const float*)d_in[17];
    float* out = (float*)d_out;

    cudaFuncSetAttribute(mma_gemm<EPI_TANH>, cudaFuncAttributeMaxDynamicSharedMemorySize, SMEM_DYN);
    cudaFuncSetAttribute(mma_gemm<EPI_RES>, cudaFuncAttributeMaxDynamicSharedMemorySize, SMEM_DYN);
    cudaFuncSetAttribute(mma_gemm<EPI_GELU>, cudaFuncAttributeMaxDynamicSharedMemorySize, SMEM_DYN);
    cudaFuncSetAttribute(mma_gemm<EPI_RES_BIAS>, cudaFuncAttributeMaxDynamicSharedMemorySize, SMEM_DYN);

    dim3 tb(32, 8);
    ln_h_kernel<true><<<Mrows, 256>>>(x, ln_g, ln_b, symh(g_nh),
                                      Wsd, bsd, Wpd, bpd, symf(g_sd), symf(g_pd));
    tsplit4_kernel<<<dim3(INNERc/32, DMc/32, 4), tb>>>(Wa, Wb, Wql, Wqr, symh(g_wp));
    {
        dim3 grid(2048/128, Mrows/128);
        mma_gemm<EPI_TANH><<<grid, 256, SMEM_DYN>>>(symh(g_nh), symh(g_wp),
            symf(g_proj), nullptr, nullptr, nullptr, Mrows, 2048, DMc);
    }
    // 4: scan phase 1 <- profiled
    scan_p1<<<dim3(128, NCHUNK), 256>>>(symf(g_proj), symf(g_sd), symf(g_pd),
        symf(g_lhat), symf(g_rt), symf(g_Qt),
        symf(g_PL), symf(g_QL), symf(g_uL), symf(g_rL), symf(g_Mhat));
    scan_p2<<<64, 256>>>(symf(g_PL), symf(g_QL), symf(g_uL), symf(g_rL),
                         symf(g_Mhat), symf(g_s0), symf(g_M0));
    scan_p3<<<dim3(Tc/64, 64), 256>>>(symf(g_proj), symf(g_lhat), symf(g_rt),
                                      symf(g_Qt), symf(g_s0), symf(g_M0), symh(g_ys));

    tsplit_kernel<<<dim3(DMc/32, INNERc/32), tb>>>(Wout, symh(g_wo), INNERc, DMc);
    {
        dim3 grid(DMc/128, Mrows/128);
        mma_gemm<EPI_RES><<<grid, 256, SMEM_DYN>>>(symh(g_ys), symh(g_wo),
            symf(g_h), nullptr, x, nullptr, Mrows, DMc, INNERc);
    }
    ln_h_kernel<false><<<Mrows, 256>>>(symf(g_h), ffn_g, ffn_b, symh(g_fin),
                                       nullptr, nullptr, nullptr, nullptr, nullptr, nullptr);
    tsplit_kernel<<<dim3(HIDc/32, DMc/32), tb>>>(W1, symh(g_w1), DMc, HIDc);
    {
        dim3 grid(HIDc/128, Mrows/128);
        mma_gemm<EPI_GELU><<<grid, 256, SMEM_DYN>>>(symh(g_fin), symh(g_w1),
            nullptr, symh(g_mid), nullptr, b1, Mrows, HIDc, DMc);
    }
    tsplit_kernel<<<dim3(DMc/32, HIDc/32), tb>>>(W2, symh(g_w2), HIDc, DMc);
    {
        dim3 grid(DMc/128, Mrows/128);
        mma_gemm<EPI_RES_BIAS><<<grid, 256, SMEM_DYN>>>(symh(g_mid), symh(g_w2),
            out, nullptr, symf(g_h), b2, Mrows, DMc, HIDc);
    }
}

// round 17
// speedup vs baseline: 1.0468x; 1.0044x over previous
#include <cuda_runtime.h>
#include <cuda_fp16.h>
#include <math.h>
#include <stdint.h>

#define Bc 8
#define Tc 2048
#define DMc 1024
#define Hc 8
#define SDc 64
#define INNERc 512
#define HIDc 4096
#define Mrows (Bc * Tc)
#define NCHUNK 16
#define CLEN 128

typedef __half fp16;

__device__ __align__(256) fp16  g_nh [(size_t)Mrows * DMc];
__device__ __align__(256) float g_proj[(size_t)Mrows * 2048];
__device__ __align__(256) float g_sd [(size_t)Mrows * Hc];
__device__ __align__(256) float g_pd [(size_t)Mrows * Hc];
__device__ __align__(256) fp16  g_ys [(size_t)Mrows * INNERc];
__device__ __align__(256) float g_h  [(size_t)Mrows * DMc];
__device__ __align__(256) fp16  g_fin[(size_t)Mrows * DMc];
__device__ __align__(256) fp16  g_mid[(size_t)Mrows * HIDc];
__device__ __align__(256) fp16 g_wp[2048*DMc];
__device__ __align__(256) fp16 g_wo[DMc*INNERc];
__device__ __align__(256) fp16 g_w1[HIDc*DMc];
__device__ __align__(256) fp16 g_w2[DMc*HIDc];
// chunked-scan intermediates
__device__ __align__(256) float2 g_lr[(size_t)64*Tc*64];   // packed (lhat, rt)
__device__ __align__(256) float g_Qt  [(size_t)64*Tc];
__device__ __align__(256) float g_PL[64*NCHUNK], g_QL[64*NCHUNK];
__device__ __align__(256) float g_uL[64*NCHUNK*64], g_rL[64*NCHUNK*64];
__device__ __align__(256) float g_Mhat[(size_t)64*NCHUNK*4096];
__device__ __align__(256) float g_s0[64*NCHUNK*64];
__device__ __align__(256) float g_M0[(size_t)64*NCHUNK*4096];

// ---------------- helpers ----------------
__device__ __forceinline__ uint32_t smem_u32(const void* p) {
    return (uint32_t)__cvta_generic_to_shared(p);
}
__device__ __forceinline__ void cp16(uint32_t dst, const void* src) {
    asm volatile("cp.async.cg.shared.global [%0], [%1], 16;\n" :: "r"(dst), "l"(src));
}
__device__ __forceinline__ void cp_commit() { asm volatile("cp.async.commit_group;\n"); }
template <int NN> __device__ __forceinline__ void cp_wait() {
    asm volatile("cp.async.wait_group %0;\n" :: "n"(NN));
}
__device__ __forceinline__ void ldm_x4(uint32_t* r, uint32_t addr) {
    asm volatile("ldmatrix.sync.aligned.m8n8.x4.shared.b16 {%0,%1,%2,%3}, [%4];"
        : "=r"(r[0]), "=r"(r[1]), "=r"(r[2]), "=r"(r[3]) : "r"(addr));
}
__device__ __forceinline__ void mma_fp16(float* d, const uint32_t* a, const uint32_t* b) {
    asm volatile("mma.sync.aligned.m16n8k16.row.col.f32.f16.f16.f32 "
        "{%0,%1,%2,%3},{%4,%5,%6,%7},{%8,%9},{%0,%1,%2,%3};"
        : "+f"(d[0]), "+f"(d[1]), "+f"(d[2]), "+f"(d[3])
        : "r"(a[0]), "r"(a[1]), "r"(a[2]), "r"(a[3]), "r"(b[0]), "r"(b[1]));
}

// ---------------- LN + fp16 out (+ optional fused sd/pd gates) --------------
template <bool GATES>
__global__ void ln_h_kernel(const float* __restrict__ X,
                            const float* __restrict__ gam,
                            const float* __restrict__ bet,
                            fp16* __restrict__ Oh,
                            const float* __restrict__ Wsd, const float* __restrict__ bsd,
                            const float* __restrict__ Wpd, const float* __restrict__ bpd,
                            float* __restrict__ SDo, float* __restrict__ PDo)
{
    int row = blockIdx.x, tid = threadIdx.x;
    const float4* xr = reinterpret_cast<const float4*>(X + (size_t)row * DMc);
    float4 v = xr[tid];
    float s = v.x + v.y + v.z + v.w;
    float q = v.x*v.x + v.y*v.y + v.z*v.z + v.w*v.w;
    int lane = tid & 31, wid = tid >> 5;
#pragma unroll
    for (int o = 16; o; o >>= 1) {
        s += __shfl_xor_sync(0xffffffffu, s, o);
        q += __shfl_xor_sync(0xffffffffu, q, o);
    }
    __shared__ float rs[8], rq[8];
    __shared__ float s_n[1024];
    __shared__ float s_part[16][17];
    if (!lane) { rs[wid] = s; rq[wid] = q; }
    __syncthreads();
    if (tid == 0) {
        float S = 0.f, Q = 0.f;
#pragma unroll
        for (int i = 0; i < 8; i++) { S += rs[i]; Q += rq[i]; }
        rs[0] = S; rq[0] = Q;
    }
    __syncthreads();
    float mu = rs[0] * (1.0f / DMc);
    float var = rq[0] * (1.0f / DMc) - mu * mu;
    float rstd = rsqrtf(var + 1e-5f);
    const float4 gg = reinterpret_cast<const float4*>(gam)[tid];
    const float4 bb = reinterpret_cast<const float4*>(bet)[tid];
    float o[4];
    o[0] = (v.x-mu)*rstd*gg.x + bb.x; o[1] = (v.y-mu)*rstd*gg.y + bb.y;
    o[2] = (v.z-mu)*rstd*gg.z + bb.z; o[3] = (v.w-mu)*rstd*gg.w + bb.w;
    size_t off = (size_t)row * DMc + tid * 4;
    __half2 h0 = __halves2half2(__float2half(o[0]), __float2half(o[1]));
    __half2 h1 = __halves2half2(__float2half(o[2]), __float2half(o[3]));
    *reinterpret_cast<uint2*>(Oh + off) = make_uint2(*(uint32_t*)&h0, *(uint32_t*)&h1);
    if (GATES) {
        *reinterpret_cast<float4*>(&s_n[tid * 4]) = make_float4(o[0], o[1], o[2], o[3]);
        __syncthreads();
        int gslot = tid & 15;
        int j = gslot & 7;
        int kc = tid >> 4;
        const float* Wg = (gslot < 8) ? Wsd : Wpd;
        float part = 0.f;
#pragma unroll 8
        for (int kk = 0; kk < 64; kk++) {
            int kx = kc * 64 + kk;
            part += s_n[kx] * Wg[(size_t)kx * Hc + j];
        }
        s_part[kc][gslot] = part;
        __syncthreads();
        if (tid < 16) {
            float sum = 0.f;
#pragma unroll
            for (int c = 0; c < 16; c++) sum += s_part[c][tid];
            int jj = tid & 7;
            float bv = (tid < 8) ? bsd[jj] : bpd[jj];
            float sig = 1.0f / (1.0f + expf(-(sum + bv)));
            float* outp = (tid < 8) ? SDo : PDo;
            outp[(size_t)row * Hc + jj] = sig;
        }
    }
}

// ---------------- weight transpose ----------------
__global__ void tsplit_kernel(const float* __restrict__ W,
                              fp16* __restrict__ Oh, int K, int N)
{
    __shared__ float t[32][33];
    int n0 = blockIdx.x * 32, k0 = blockIdx.y * 32;
    int tx = threadIdx.x, ty = threadIdx.y;
#pragma unroll
    for (int j = 0; j < 32; j += 8)
        t[ty + j][tx] = W[(size_t)(k0 + ty + j) * N + n0 + tx];
    __syncthreads();
#pragma unroll
    for (int j = 0; j < 32; j += 8)
        Oh[(size_t)(n0 + ty + j) * K + k0 + tx] = __float2half(t[tx][ty + j]);
}

__global__ void tsplit4_kernel(const float* __restrict__ Wa, const float* __restrict__ Wb,
                               const float* __restrict__ Wql, const float* __restrict__ Wqr,
                               fp16* __restrict__ Oh)
{
    int z = blockIdx.z;
    const float* W = (z == 0) ? Wa : (z == 1) ? Wb : (z == 2) ? Wql : Wqr;
    __shared__ float t[32][33];
    int n0 = blockIdx.x * 32, k0 = blockIdx.y * 32;
    int tx = threadIdx.x, ty = threadIdx.y;
#pragma unroll
    for (int j = 0; j < 32; j += 8)
        t[ty + j][tx] = W[(size_t)(k0 + ty + j) * INNERc + n0 + tx];
    __syncthreads();
#pragma unroll
    for (int j = 0; j < 32; j += 8)
        Oh[(size_t)(z * INNERc + n0 + ty + j) * DMc + k0 + tx] = __float2half(t[tx][ty + j]);
}

// ---------------- mma.sync fp16 GEMM (unchanged, measured ceiling) -----------
enum { EPI_TANH = 1, EPI_RES = 2, EPI_GELU = 3, EPI_RES_BIAS = 4 };
#define LDB 144u
#define MATB 18432u
#define STAGEB 36864u
#define NSTAGE 3
#define SMEM_DYN (3 * 36864)

template <int EPI>
__global__ __launch_bounds__(256)
void mma_gemm(const fp16* __restrict__ A, const fp16* __restrict__ B,
              float* __restrict__ C, fp16* __restrict__ Oh,
              const float* __restrict__ res, const float* __restrict__ bias,
              int M, int N, int K)
{
    extern __shared__ char smraw[];
    uint32_t sbase = smem_u32(smraw);
    int tid = threadIdx.x, lane = tid & 31, wid = tid >> 5;
    int warp_m = wid & 3, warp_n = wid >> 2;
    int bm = blockIdx.y * 128, bn = blockIdx.x * 128;

    float acc[2][8][4];
#pragma unroll
    for (int a = 0; a < 2; a++)
#pragma unroll
        for (int b = 0; b < 8; b++)
#pragma unroll
            for (int c = 0; c < 4; c++) acc[a][b][c] = 0.f;

    auto load_stage = [&](int c) {
        int k0 = c * 64;
        uint32_t st = sbase + (uint32_t)(c % NSTAGE) * STAGEB;
#pragma unroll
        for (int i = 0; i < 8; i++) {
            int id = tid + i * 256;
            int mat = id >> 10, rem = id & 1023;
            int r = rem >> 3, g = rem & 7;
            const fp16* src = mat ? B : A;
            int row = (mat ? bn : bm) + r;
            cp16(st + (uint32_t)mat * MATB + (uint32_t)r * LDB + (uint32_t)g * 16u,
                 src + (size_t)row * K + k0 + g * 8);
        }
        cp_commit();
    };

    int NC = K / 64;
    load_stage(0);
    load_stage(1);

    uint32_t a_off = (uint32_t)(warp_m * 32 + (lane & 15)) * LDB + (uint32_t)((lane >> 4) << 4);
    int bg = lane >> 3, bt = lane & 7;
    uint32_t b_off = (uint32_t)(warp_n * 64 + ((bg >> 1) << 3) + bt) * LDB + (uint32_t)((bg & 1) << 4);

    for (int c = 0; c < NC; c++) {
        cp_wait<1>();
        __syncthreads();
        if (c + 2 < NC) load_stage(c + 2);
        uint32_t st = sbase + (uint32_t)(c % NSTAGE) * STAGEB;
#pragma unroll
        for (int ks = 0; ks < 4; ks++) {
            uint32_t koff = (uint32_t)(ks << 5);
            uint32_t ar[2][4];
#pragma unroll
            for (int mt = 0; mt < 2; mt++)
                ldm_x4(ar[mt], st + a_off + (uint32_t)(mt * 16) * LDB + koff);
            uint32_t br[8][2];
#pragma unroll
            for (int jj = 0; jj < 4; jj++) {
                uint32_t r4[4];
                ldm_x4(r4, st + MATB + b_off + (uint32_t)(jj * 16) * LDB + koff);
                br[jj*2][0] = r4[0]; br[jj*2][1] = r4[1];
                br[jj*2+1][0] = r4[2]; br[jj*2+1][1] = r4[3];
            }
#pragma unroll
            for (int mt = 0; mt < 2; mt++)
#pragma unroll
                for (int nt = 0; nt < 8; nt++)
                    mma_fp16(acc[mt][nt], ar[mt], br[nt]);
        }
    }

#pragma unroll
    for (int mt = 0; mt < 2; mt++)
#pragma unroll
        for (int nt = 0; nt < 8; nt++) {
            int col = bn + warp_n * 64 + nt * 8 + (lane & 3) * 2;
            int r0 = bm + warp_m * 32 + mt * 16 + (lane >> 2);
#pragma unroll
            for (int hr = 0; hr < 2; hr++) {
                int m = r0 + hr * 8;
                float v0 = acc[mt][nt][hr*2+0], v1 = acc[mt][nt][hr*2+1];
                size_t off = (size_t)m * N + col;
                if (EPI == EPI_GELU) {
                    float2 bb = *reinterpret_cast<const float2*>(&bias[col]);
                    v0 += bb.x; v1 += bb.y;
                    const float is2 = 0.70710678118654752f;
                    v0 = 0.5f * v0 * (1.f + erff(v0 * is2));
                    v1 = 0.5f * v1 * (1.f + erff(v1 * is2));
                    __half2 hh = __halves2half2(__float2half(v0), __float2half(v1));
                    *reinterpret_cast<uint32_t*>(&Oh[off]) = *(uint32_t*)&hh;
                } else {
                    if (EPI == EPI_TANH) { v0 = tanhf(v0); v1 = tanhf(v1); }
                    else if (EPI == EPI_RES) {
                        float2 rr = *reinterpret_cast<const float2*>(&res[off]);
                        v0 += rr.x; v1 += rr.y;
                    } else if (EPI == EPI_RES_BIAS) {
                        float2 rr = *reinterpret_cast<const float2*>(&res[off]);
                        float2 bb = *reinterpret_cast<const float2*>(&bias[col]);
                        v0 += rr.x + bb.x; v1 += rr.y + bb.y;
                    }
                    *reinterpret_cast<float2*>(&C[off]) = make_float2(v0, v1);
                }
            }
        }
}

// ---------------- scan phase 1: per-chunk partial scan (zero init) -----------
// grid (128, NCHUNK): x = es(2) x h(8) x b(8), y = chunk. 256 threads = 8 warps.
__global__ __launch_bounds__(256, 4)
void scan_p1(const float* __restrict__ P,
             const float* __restrict__ SDg, const float* __restrict__ PDg,
             float2* __restrict__ LR, float* __restrict__ QT,
             float* __restrict__ PLa, float* __restrict__ QLa,
             float* __restrict__ ULa, float* __restrict__ RLa,
             float* __restrict__ MHAT)
{
    int blk = blockIdx.x, cch = blockIdx.y;
    int es = blk & 1, h = (blk >> 1) & 7, b = blk >> 4;
    int stream = b * 8 + h;
    int tid = threadIdx.x, w = tid >> 5, lane = tid & 31;
    int eidx = lane & 3, dg = lane >> 2;
    int e_loc = es * 32 + w * 4 + eidx;
    int d0 = dg * 8;
    int tC = cch * CLEN;

    __shared__ float s_a [2][8][68];
    __shared__ float s_ql[2][8][68];
    __shared__ float s_b [2][8][32];
    __shared__ float s_sp[2][8][2];

    size_t Pbase = ((size_t)b * Tc) * 2048 + (size_t)h * SDc;
    size_t spb   = ((size_t)b * Tc) * Hc + h;

    auto load_batch = [&](int t0, float* r) {
#pragma unroll
        for (int i = 0; i < 6; i++) {
            int f = tid + i * 256;
            float v = 0.f;
            if (f < 512) {
                int j = f >> 6, d = f & 63;
                v = P[Pbase + (size_t)(t0 + j) * 2048 + d];
            } else if (f < 1024) {
                int g = f - 512; int j = g >> 6, d = g & 63;
                v = P[Pbase + (size_t)(t0 + j) * 2048 + 1024 + d];
            } else if (f < 1280) {
                int g = f - 1024; int j = g >> 5, e = g & 31;
                v = P[Pbase + (size_t)(t0 + j) * 2048 + 512 + es * 32 + e];
            } else if (f < 1296) {
                int g = f - 1280; int j = g >> 1;
                v = (g & 1) ? PDg[spb + (size_t)(t0 + j) * Hc]
                            : SDg[spb + (size_t)(t0 + j) * Hc];
            }
            r[i] = v;
        }
    };
    auto store_batch = [&](int buf, const float* r) {
#pragma unroll
        for (int i = 0; i < 6; i++) {
            int f = tid + i * 256;
            if (f < 512) {
                int j = f >> 6, d = f & 63;
                s_a[buf][j][d + ((d >> 5) << 2)] = r[i];
            } else if (f < 1024) {
                int g = f - 512; int j = g >> 6, d = g & 63;
                s_ql[buf][j][d + ((d >> 5) << 2)] = r[i];
            } else if (f < 1280) {
                int g = f - 1024;
                s_b[buf][g >> 5][g & 31] = r[i];
            } else if (f < 1296) {
                int g = f - 1280;
                s_sp[buf][g >> 1][g & 1] = r[i];
            }
        }
    };

    float pair[8], state[8];
#pragma unroll
    for (int i = 0; i < 8; i++) { pair[i] = 0.f; state[i] = 0.f; }
    float rgate = 0.f, Pp = 1.f, Qq = 1.f;

    float rr[2][6];
    {
        float ra[6];
        load_batch(tC, ra);
        store_batch(0, ra);
    }
    load_batch(tC + 8, rr[0]);
    __syncthreads();

    int sbidx = d0 + ((dg >> 2) << 2);
    int ecol = w * 4 + eidx;

    for (int k = 0; k < CLEN / 8; k++) {
        int buf = k & 1;
        int t0 = tC + k * 8;
        if (k < CLEN / 8 - 2) load_batch(t0 + 16, rr[buf ^ 1]);
        if (k < CLEN / 8 - 1) store_batch(buf ^ 1, rr[buf]);
        float accv[8], rv[8], Qv[8];
#pragma unroll
        for (int j = 0; j < 8; j++) {
            float sd = s_sp[buf][j][0], pd = s_sp[buf][j][1];
            float bv = s_b[buf][j][ecol];
            rgate = pd * rgate + (1.f - pd) * Pp * bv;
            rv[j] = rgate;
            Pp *= sd; Qq *= pd; Qv[j] = Qq;
            float4 q0 = *reinterpret_cast<const float4*>(&s_ql[buf][j][sbidx]);
            float4 q1 = *reinterpret_cast<const float4*>(&s_ql[buf][j][sbidx + 4]);
            float4 a0 = *reinterpret_cast<const float4*>(&s_a[buf][j][sbidx]);
            float4 a1 = *reinterpret_cast<const float4*>(&s_a[buf][j][sbidx + 4]);
            float qlv[8] = {q0.x,q0.y,q0.z,q0.w,q1.x,q1.y,q1.z,q1.w};
            float av[8]  = {a0.x,a0.y,a0.z,a0.w,a1.x,a1.y,a1.z,a1.w};
            float ompd_b = (1.f - pd) * bv;
            float acc = 0.f;
#pragma unroll
            for (int i = 0; i < 8; i++) {
                pair[i] = pd * pair[i] + ompd_b * state[i];
                acc += pair[i] * qlv[i];
            }
            float oms = 1.f - sd;
#pragma unroll
            for (int i = 0; i < 8; i++)
                state[i] = sd * state[i] + oms * av[i];
            accv[j] = acc;
        }
#pragma unroll
        for (int j = 0; j < 8; j++) accv[j] += __shfl_xor_sync(0xffffffffu, accv[j], 4);
#pragma unroll
        for (int j = 0; j < 8; j++) accv[j] += __shfl_xor_sync(0xffffffffu, accv[j], 8);
#pragma unroll
        for (int j = 0; j < 8; j++) accv[j] += __shfl_xor_sync(0xffffffffu, accv[j], 16);
        if (dg == 0) {
#pragma unroll
            for (int j = 0; j < 8; j++) {
                size_t pidx = ((size_t)stream * Tc + (t0 + j)) * 64 + e_loc;
                LR[pidx] = make_float2(accv[j], rv[j]);
            }
        }
        if (es == 0 && tid == 0) {
#pragma unroll
            for (int j = 0; j < 8; j++)
                QT[(size_t)stream * Tc + t0 + j] = Qv[j];
        }
        __syncthreads();
    }

    size_t bidx = (size_t)(stream * NCHUNK + cch);
    if (es == 0 && tid == 0) { PLa[bidx] = Pp; QLa[bidx] = Qq; }
    if (es == 0 && w == 0 && eidx == 0) {
#pragma unroll
        for (int i = 0; i < 8; i++) ULa[bidx * 64 + d0 + i] = state[i];
    }
    if (dg == 0) RLa[bidx * 64 + e_loc] = rgate;
#pragma unroll
    for (int i = 0; i < 8; i++)
        MHAT[(bidx << 12) + (size_t)(d0 + i) * 64 + e_loc] = pair[i];
}

// ---------------- scan phase 2: boundary propagation (tiny) ------------------
__global__ __launch_bounds__(256)
void scan_p2(const float* __restrict__ PLa, const float* __restrict__ QLa,
             const float* __restrict__ ULa, const float* __restrict__ RLa,
             const float* __restrict__ MHAT,
             float* __restrict__ S0a, float* __restrict__ M0a)
{
    int stream = blockIdx.x, tid = threadIdx.x;
    __shared__ float s0[64];
    float m[16];
#pragma unroll
    for (int i = 0; i < 16; i++) m[i] = 0.f;
    if (tid < 64) s0[tid] = 0.f;
    __syncthreads();
    int d_ = tid >> 2, e0 = (tid & 3) * 16;
    for (int c = 0; c < NCHUNK; c++) {
        size_t bidx = (size_t)(stream * NCHUNK + c);
        if (tid < 64) S0a[bidx * 64 + tid] = s0[tid];
#pragma unroll
        for (int i = 0; i < 16; i++)
            M0a[(bidx << 12) + (size_t)d_ * 64 + e0 + i] = m[i];
        float QL = QLa[bidx], PL = PLa[bidx];
        float s0d = s0[d_];
#pragma unroll
        for (int i = 0; i < 16; i++)
            m[i] = QL * m[i] + s0d * RLa[bidx * 64 + e0 + i]
                 + MHAT[(bidx << 12) + (size_t)d_ * 64 + e0 + i];
        __syncthreads();
        if (tid < 64) s0[tid] = PL * s0[tid] + ULa[bidx * 64 + tid];
        __syncthreads();
    }
}

// ---------------- scan phase 3: parallel correction + output -----------------
// grid (32, 64): x = t-tile of 64 steps, y = stream. 256 thr: tg=tid>>6, e=tid&63.
__global__ __launch_bounds__(256)
void scan_p3(const float* __restrict__ Pr,
             const float2* __restrict__ LR, const float* __restrict__ QT,
             const float* __restrict__ S0a, const float* __restrict__ M0a,
             fp16* __restrict__ Y)
{
    int tt0 = blockIdx.x * 64;
    int stream = blockIdx.y;
    int cch = tt0 / CLEN;
    int b = stream >> 3, h = stream & 7;
    int tid = threadIdx.x, tg = tid >> 6, e = tid & 63;
    __shared__ float sM0[64][64];
    __shared__ float sql[64][64];
    __shared__ float ss0[64];
    __shared__ float sdot[64];
    size_t bidx = (size_t)(stream * NCHUNK + cch);
#pragma unroll
    for (int i = 0; i < 16; i++) {
        int f = tid + i * 256;
        sM0[f >> 6][f & 63] = M0a[(bidx << 12) + f];
    }
    if (tid < 64) ss0[tid] = S0a[bidx * 64 + tid];
    size_t Pbase = ((size_t)b * Tc) * 2048 + (size_t)h * SDc;
#pragma unroll
    for (int i = 0; i < 16; i++) {
        int f = tid + i * 256;
        int tloc = f >> 6, d = f & 63;
        sql[tloc][d] = Pr[Pbase + (size_t)(tt0 + tloc) * 2048 + 1024 + d];
    }
    __syncthreads();
    if (tid < 64) {
        float dd = 0.f;
#pragma unroll 8
        for (int d = 0; d < 64; d++) dd += ss0[d] * sql[tid][d];
        sdot[tid] = dd;
    }
    __syncthreads();
    float mv[16];
#pragma unroll
    for (int kk = 0; kk < 16; kk++) mv[kk] = 0.f;
    int tbase = tg * 16;
#pragma unroll 4
    for (int d = 0; d < 64; d++) {
        float m0 = sM0[d][e];
#pragma unroll
        for (int kk = 0; kk < 16; kk++)
            mv[kk] += m0 * sql[tbase + kk][d];
    }
    size_t outb = ((size_t)b * Tc) * INNERc + (size_t)h * SDc + e;
#pragma unroll
    for (int kk = 0; kk < 16; kk++) {
        int tloc = tbase + kk;
        int t = tt0 + tloc;
        size_t pidx = (size_t)stream * Tc + t;
        float2 lr = LR[pidx * 64 + e];
        float Qv = QT[pidx];
        float qr = Pr[Pbase + (size_t)t * 2048 + 1536 + e];
        float outv = qr * (Qv * mv[kk] + sdot[tloc] * lr.y + lr.x);
        Y[outb + (size_t)t * INNERc] = __float2half(outv);
    }
}

// ---------------- launch ----------------
static float* symf(const void* s) { void* p = 0; cudaGetSymbolAddress(&p, s); return (float*)p; }
static float2* symf2(const void* s) { void* p = 0; cudaGetSymbolAddress(&p, s); return (float2*)p; }
static fp16*  symh(const void* s) { void* p = 0; cudaGetSymbolAddress(&p, s); return (fp16*)p; }

extern "C" void kernel_launch(void* const* d_in, const int* in_sizes, int n_in,
                              void* d_out, int out_size)
{
    const float* x    = (const float*)d_in[0];
    const float* ln_g = (const float*)d_in[1];
    const float* ln_b = (const float*)d_in[2];
    const float* ffn_g= (const float*)d_in[3];
    const float* ffn_b= (const float*)d_in[4];
    const float* Wa   = (const float*)d_in[5];
    const float* Wb   = (const float*)d_in[6];
    const float* Wql  = (const float*)d_in[7];
    const float* Wqr  = (const float*)d_in[8];
    const float* Wsd  = (const float*)d_in[9];
    const float* bsd  = (const float*)d_in[10];
    const float* Wpd  = (const float*)d_in[11];
    const float* bpd  = (const float*)d_in[12];
    const float* Wout = (const float*)d_in[13];
    const float* W1   = (const float*)d_in[14];
    const float* b1   = (const float*)d_in[15];
    const float* W2   = (const float*)d_in[16];
    const float* b2   = (const float*)d_in[17];
    float* out = (float*)d_out;

    cudaFuncSetAttribute(mma_gemm<EPI_TANH>, cudaFuncAttributeMaxDynamicSharedMemorySize, SMEM_DYN);
    cudaFuncSetAttribute(mma_gemm<EPI_RES>, cudaFuncAttributeMaxDynamicSharedMemorySize, SMEM_DYN);
    cudaFuncSetAttribute(mma_gemm<EPI_GELU>, cudaFuncAttributeMaxDynamicSharedMemorySize, SMEM_DYN);
    cudaFuncSetAttribute(mma_gemm<EPI_RES_BIAS>, cudaFuncAttributeMaxDynamicSharedMemorySize, SMEM_DYN);

    dim3 tb(32, 8);
    ln_h_kernel<true><<<Mrows, 256>>>(x, ln_g, ln_b, symh(g_nh),
                                      Wsd, bsd, Wpd, bpd, symf(g_sd), symf(g_pd));
    tsplit4_kernel<<<dim3(INNERc/32, DMc/32, 4), tb>>>(Wa, Wb, Wql, Wqr, symh(g_wp));
    {
        dim3 grid(2048/128, Mrows/128);
        mma_gemm<EPI_TANH><<<grid, 256, SMEM_DYN>>>(symh(g_nh), symh(g_wp),
            symf(g_proj), nullptr, nullptr, nullptr, Mrows, 2048, DMc);
    }
    // 4: scan phase 1 <- profiled
    scan_p1<<<dim3(128, NCHUNK), 256>>>(symf(g_proj), symf(g_sd), symf(g_pd),
        symf2(g_lr), symf(g_Qt),
        symf(g_PL), symf(g_QL), symf(g_uL), symf(g_rL), symf(g_Mhat));
    scan_p2<<<64, 256>>>(symf(g_PL), symf(g_QL), symf(g_uL), symf(g_rL),
                         symf(g_Mhat), symf(g_s0), symf(g_M0));
    scan_p3<<<dim3(Tc/64, 64), 256>>>(symf(g_proj), symf2(g_lr),
                                      symf(g_Qt), symf(g_s0), symf(g_M0), symh(g_ys));

    tsplit_kernel<<<dim3(DMc/32, INNERc/32), tb>>>(Wout, symh(g_wo), INNERc, DMc);
    {
        dim3 grid(DMc/128, Mrows/128);
        mma_gemm<EPI_RES><<<grid, 256, SMEM_DYN>>>(symh(g_ys), symh(g_wo),
            symf(g_h), nullptr, x, nullptr, Mrows, DMc, INNERc);
    }
    ln_h_kernel<false><<<Mrows, 256>>>(symf(g_h), ffn_g, ffn_b, symh(g_fin),
                                       nullptr, nullptr, nullptr, nullptr, nullptr, nullptr);
    tsplit_kernel<<<dim3(HIDc/32, DMc/32), tb>>>(W1, symh(g_w1), DMc, HIDc);
    {
        dim3 grid(HIDc/128, Mrows/128);
        mma_gemm<EPI_GELU><<<grid, 256, SMEM_DYN>>>(symh(g_fin), symh(g_w1),
            nullptr, symh(g_mid), nullptr, b1, Mrows, HIDc, DMc);
    }
    tsplit_kernel<<<dim3(DMc/32, HIDc/32), tb>>>(W2, symh(g_w2), HIDc, DMc);
    {
        dim3 grid(DMc/128, Mrows/128);
        mma_gemm<EPI_RES_BIAS><<<grid, 256, SMEM_DYN>>>(symh(g_mid), symh(g_w2),
            out, nullptr, symf(g_h), b2, Mrows, DMc, HIDc);
    }
}